// round 15
// baseline (speedup 1.0000x reference)
#include <cuda_runtime.h>
#include <math.h>

// Shapes (fixed by the problem)
#define B 32
#define C 256
#define H 64
#define W 64
#define HW (H*W)            // 4096
#define PLANES (B*C)        // 8192
#define RH 3                // int(0.05*64)
#define RW 6                // int(0.1*64)
#define CLAMP_SX 61.0f      // h - rh
#define CLAMP_SY 58.0f      // w - rw

#define PREFETCH_L2(p) asm volatile("prefetch.global.L2 [%0];" :: "l"(p))

// Scratch (no cudaMalloc allowed)
__device__ float g_mean[PLANES];
__device__ float g_scale[PLANES];
__device__ float g_vh[2 * B * 256];    // [branch][batch][channel]
__device__ float g_th1[2 * B * 64];    // [branch][batch][hidden]

__device__ __forceinline__ float sigmoidf_acc(float v) {
    return 1.0f / (1.0f + expf(-v));
}
__device__ __forceinline__ float warp_red(float s) {
#pragma unroll
    for (int o = 16; o; o >>= 1) s += __shfl_xor_sync(0xffffffffu, s, o);
    return s;   // all lanes hold the total (xor butterfly)
}

// ---------------------------------------------------------------------------
// Kernel 1: per-(b,c) mean (R14 geometry: 512 thr, 4 planes/block, 8
// streaming float4 loads per thread). First 18 blocks also prefetch the
// ~1.2MB weight set into L2; x loads are __ldcs (evict-first) so the
// weights survive the 134MB stream.
// ---------------------------------------------------------------------------
__global__ void __launch_bounds__(512) k_mean(
    const float* __restrict__ x,
    const float* __restrict__ ch_w, const float* __restrict__ cw_w,
    const float* __restrict__ dh_fc1w, const float* __restrict__ dw_fc1w,
    const float* __restrict__ dh_fc2w, const float* __restrict__ dw_fc2w)
{
    const int bid = blockIdx.x;
    const int tid = threadIdx.x;

    if (bid < 18) {   // L2 warm of weights for k_mlp / k_apply
        const char* p;
        int off;
        if      (bid < 4)  { p = (const char*)ch_w;    off = bid * 512; }
        else if (bid < 8)  { p = (const char*)cw_w;    off = (bid - 4) * 512; }
        else if (bid < 12) { p = (const char*)dh_fc2w; off = (bid - 8) * 512; }
        else if (bid < 16) { p = (const char*)dw_fc2w; off = (bid - 12) * 512; }
        else if (bid == 16){ p = (const char*)dh_fc1w; off = 0; }
        else               { p = (const char*)dw_fc1w; off = 0; }
        PREFETCH_L2(p + (size_t)(off + tid) * 128);
    }

    const int sub = tid >> 7;        // 0..3: plane within block
    const int t   = tid & 127;       // 0..127 within plane
    const int wid  = tid >> 5;       // 0..15
    const int lane = tid & 31;
    const int plane = bid * 4 + sub;

    const float4* xp = reinterpret_cast<const float4*>(x) + (size_t)plane * (HW / 4);

    float4 v[8];
#pragma unroll
    for (int i = 0; i < 8; i++) v[i] = __ldcs(xp + t + i * 128);

    float s = 0.f;
#pragma unroll
    for (int i = 0; i < 8; i++) s += (v[i].x + v[i].y) + (v[i].z + v[i].w);
    s = warp_red(s);

    __shared__ float ws[16];
    if (lane == 0) ws[wid] = s;
    __syncthreads();
    if (t == 0) {
        float tot = ws[sub * 4] + ws[sub * 4 + 1] + ws[sub * 4 + 2] + ws[sub * 4 + 3];
        g_mean[plane] = tot * (1.0f / (float)HW);
    }
}

// ---------------------------------------------------------------------------
// Kernel 2: SHORT MLP — only SE + vh + th1 (fc2 + dyrelu moved into k_apply).
// grid = (B, 2), 512 threads = 16 warps. Publishes g_scale, g_vh, g_th1.
// ---------------------------------------------------------------------------
__global__ void __launch_bounds__(512) k_mlp(
    const float* __restrict__ se_w1,   // (16,256)
    const float* __restrict__ se_w2,   // (256,16)
    const float* __restrict__ ch_w, const float* __restrict__ ch_b,
    const float* __restrict__ cw_w, const float* __restrict__ cw_b,
    const float* __restrict__ dh_fc1w, const float* __restrict__ dh_fc1b,
    const float* __restrict__ dw_fc1w, const float* __restrict__ dw_fc1b)
{
    __shared__ float y[256];
    __shared__ float t1[16];
    __shared__ float gv[256];
    __shared__ float vh[256];

    int b    = blockIdx.x;
    int br   = blockIdx.y;
    int tid  = threadIdx.x;
    int wid  = tid >> 5;          // 0..15
    int lane = tid & 31;

    const float* cw   = br ? cw_w    : ch_w;
    const float* cb   = br ? cw_b    : ch_b;
    const float* fc1w = br ? dw_fc1w : dh_fc1w;
    const float* fc1b = br ? dw_fc1b : dh_fc1b;

    if (tid < 256) y[tid] = g_mean[b * 256 + tid];
    __syncthreads();

    float yreg[8];
#pragma unroll
    for (int k = 0; k < 8; k++) yreg[k] = y[lane + k * 32];

    // SE squeeze: 1 output per warp
    {
        const float* r = se_w1 + wid * 256;
        float s = 0.f;
#pragma unroll
        for (int k = 0; k < 8; k++) s = fmaf(yreg[k], r[lane + k * 32], s);
        s = warp_red(s);
        if (lane == 0) t1[wid] = fmaxf(s, 0.f);
    }
    __syncthreads();

    // SE excite
    if (tid < 256) {
        const float4* r = reinterpret_cast<const float4*>(se_w2 + tid * 16);
        const float4* t = reinterpret_cast<const float4*>(t1);
        float s = 0.f;
#pragma unroll
        for (int j = 0; j < 4; j++) {
            float4 wv = r[j];
            float4 tv = t[j];
            s = fmaf(wv.x, tv.x, fmaf(wv.y, tv.y, fmaf(wv.z, tv.z, fmaf(wv.w, tv.w, s))));
        }
        float sg = sigmoidf_acc(s);
        if (br == 0) g_scale[b * 256 + tid] = sg;
        gv[tid] = y[tid] * sg;
    }
    __syncthreads();

    float greg[8];
#pragma unroll
    for (int k = 0; k < 8; k++) greg[k] = gv[lane + k * 32];

    // vh[256] = gv @ cw^T + cb : 16 outputs per warp; publish to smem + global
#pragma unroll 8
    for (int i = 0; i < 16; i++) {
        int o = wid * 16 + i;
        const float* r = cw + o * 256;
        float s = 0.f;
#pragma unroll
        for (int k = 0; k < 8; k++) s = fmaf(greg[k], r[lane + k * 32], s);
        s = warp_red(s);
        if (lane == 0) {
            float val = s + cb[o];
            vh[o] = val;
            g_vh[(br * B + b) * 256 + o] = val;
        }
    }
    __syncthreads();

    float vreg[8];
#pragma unroll
    for (int k = 0; k < 8; k++) vreg[k] = vh[lane + k * 32];

    // th1[64] = relu(vh @ fc1w^T + fc1b) : 4 outputs per warp; publish
#pragma unroll
    for (int i = 0; i < 4; i++) {
        int o = wid * 4 + i;
        const float* r = fc1w + o * 256;
        float s = 0.f;
#pragma unroll
        for (int k = 0; k < 8; k++) s = fmaf(vreg[k], r[lane + k * 32], s);
        s = warp_red(s);
        if (lane == 0) g_th1[(br * B + b) * 64 + o] = fmaxf(s + fc1b[o], 0.f);
    }
}

// ---------------------------------------------------------------------------
// Kernel 3: out = x * scale * !inside, WITH per-block fc2 + dyrelu computed
// inside the streaming-load shadow. 512 threads, 4 planes/block.
// Warps 0-7: one (plane, branch) each -> 4 warp-reduced dot-64s + dyrelu.
// ---------------------------------------------------------------------------
__global__ void __launch_bounds__(512) k_apply(
    const float* __restrict__ x, float* __restrict__ out,
    const float* __restrict__ dh_fc2w, const float* __restrict__ dh_fc2b,
    const float* __restrict__ dw_fc2w, const float* __restrict__ dw_fc2b)
{
    const int sub  = threadIdx.x >> 7;       // 0..3: plane within block
    const int t    = threadIdx.x & 127;      // 0..127 within plane
    const int wid  = threadIdx.x >> 5;       // 0..15
    const int lane = threadIdx.x & 31;
    const int plane = blockIdx.x * 4 + sub;
    const int batch = plane >> 8;

    const float4* xp = reinterpret_cast<const float4*>(x) + (size_t)plane * (HW / 4);
    float4* op = reinterpret_cast<float4*>(out) + (size_t)plane * (HW / 4);

    // Front-issue all streaming loads — fc2/dyrelu hides in their shadow.
    float4 v[8];
#pragma unroll
    for (int i = 0; i < 8; i++) v[i] = __ldcs(xp + t + i * 128);

    __shared__ float s_th1[2][64];
    __shared__ int   s_mask[2][4];           // [branch][sub] -> sx / sy

    if (threadIdx.x < 128) {
        int br  = threadIdx.x >> 6;
        int idx = threadIdx.x & 63;
        s_th1[br][idx] = g_th1[(br * B + batch) * 64 + idx];
    }
    __syncthreads();

    if (wid < 8) {
        int psub = wid >> 1;
        int br   = wid & 1;
        int pl   = blockIdx.x * 4 + psub;
        int c    = pl & 255;

        const float* fc2w = br ? dw_fc2w : dh_fc2w;
        const float* fc2b = br ? dw_fc2b : dh_fc2b;

        float t1a = s_th1[br][lane * 2];
        float t1b = s_th1[br][lane * 2 + 1];

        float th[4];
#pragma unroll
        for (int k = 0; k < 4; k++) {
            int m = c * 4 + k;
            float2 wv = reinterpret_cast<const float2*>(fc2w + m * 64)[lane];
            float s = fmaf(t1a, wv.x, t1b * wv.y);
            s = warp_red(s);                 // all lanes hold the sum
            th[k] = 2.0f * sigmoidf_acc(s + fc2b[m]) - 1.0f;
        }

        float vv = g_vh[(br * B + batch) * 256 + c];
        // LAMBDAS=[1,1,.5,.5], INIT_V=[1,0,0,0]
        float a0 = th[0] + 1.0f, a1 = th[1];
        float b0 = 0.5f * th[2], b1 = 0.5f * th[3];
        float dy = fmaxf(fmaf(vv, a0, b0), fmaf(vv, a1, b1));
        float sg = sigmoidf_acc(dy);
        float clampv = br ? CLAMP_SY : CLAMP_SX;
        if (lane == 0) s_mask[br][psub] = (int)fminf(ceilf(64.0f * sg), clampv);
    }
    __syncthreads();

    const float sc = g_scale[plane];
    const int sx = s_mask[0][sub];
    const int sy = s_mask[1][sub];

#pragma unroll
    for (int i = 0; i < 8; i++) {
        int p = t + i * 128;        // float4 index within plane
        int row = p >> 4;           // (p*4) / 64
        int col = (p & 15) * 4;     // (p*4) % 64
        v[i].x *= sc; v[i].y *= sc; v[i].z *= sc; v[i].w *= sc;
        if (row >= sx && row < sx + RH) {
            if (col + 0 >= sy && col + 0 < sy + RW) v[i].x = 0.f;
            if (col + 1 >= sy && col + 1 < sy + RW) v[i].y = 0.f;
            if (col + 2 >= sy && col + 2 < sy + RW) v[i].z = 0.f;
            if (col + 3 >= sy && col + 3 < sy + RW) v[i].w = 0.f;
        }
        __stcs(op + p, v[i]);
    }
}

// ---------------------------------------------------------------------------
extern "C" void kernel_launch(void* const* d_in, const int* in_sizes, int n_in,
                              void* d_out, int out_size) {
    const float* x       = (const float*)d_in[0];
    const float* se_w1   = (const float*)d_in[1];
    const float* se_w2   = (const float*)d_in[2];
    const float* ch_w    = (const float*)d_in[3];
    const float* ch_b    = (const float*)d_in[4];
    const float* cw_w    = (const float*)d_in[5];
    const float* cw_b    = (const float*)d_in[6];
    const float* dh_fc1w = (const float*)d_in[7];
    const float* dh_fc1b = (const float*)d_in[8];
    const float* dh_fc2w = (const float*)d_in[9];
    const float* dh_fc2b = (const float*)d_in[10];
    const float* dw_fc1w = (const float*)d_in[11];
    const float* dw_fc1b = (const float*)d_in[12];
    const float* dw_fc2w = (const float*)d_in[13];
    const float* dw_fc2b = (const float*)d_in[14];
    float* out = (float*)d_out;

    k_mean<<<PLANES / 4, 512>>>(x, ch_w, cw_w, dh_fc1w, dw_fc1w, dh_fc2w, dw_fc2w);
    dim3 mg(B, 2);
    k_mlp<<<mg, 512>>>(se_w1, se_w2, ch_w, ch_b, cw_w, cw_b,
                       dh_fc1w, dh_fc1b, dw_fc1w, dw_fc1b);
    k_apply<<<PLANES / 4, 512>>>(x, out, dh_fc2w, dh_fc2b, dw_fc2w, dw_fc2b);
}